// round 13
// baseline (speedup 1.0000x reference)
#include <cuda_runtime.h>
#include <cuda_fp16.h>
#include <cstdint>

#define NMAX 50000
#define EMAX 800000
#define HID 128
#define NHEAD 4
#define SCAN_BLK 1024
#define SCAN_NB ((NMAX + SCAN_BLK - 1) / SCAN_BLK)
#define NCHUNK 4

// ---------------- scratch (device globals; allocation-free) ----------------
// layer-1 buffers
__device__ float  g_h[(size_t)NMAX * HID];
__device__ __half g_h16[(size_t)NMAX * HID];
__device__ float  g_as[(size_t)NMAX * NHEAD];
__device__ float  g_ad[(size_t)NMAX * NHEAD];
// layer-2 buffers (double-buffered so gemm2 chunks can overlap agg1 chunks)
__device__ float  g_hB[(size_t)NMAX * HID];
__device__ __half g_h16B[(size_t)NMAX * HID];
__device__ float  g_asB[(size_t)NMAX * NHEAD];
__device__ float  g_adB[(size_t)NMAX * NHEAD];

__device__ float  g_feat[(size_t)NMAX * HID];
__device__ float  g_gmax[2 * NHEAD];
__device__ int    g_deg[NMAX];
__device__ int    g_rowptr[NMAX + 1];
__device__ int    g_cursor[NMAX];
__device__ int    g_csr_src[EMAX];
__device__ int    g_bsum[SCAN_NB];
__device__ int    g_boff[SCAN_NB];

__device__ __forceinline__ float lrelu02(float v) { return v > 0.f ? v : 0.2f * v; }

__device__ __forceinline__ void atomicMaxF(float* a, float v) {
    if (v >= 0.f) atomicMax((int*)a, __float_as_int(v));
    else          atomicMin((unsigned int*)a, __float_as_uint(v));
}

__device__ __forceinline__ unsigned f2tf32(float f) {
    unsigned u;
    asm("cvt.rna.tf32.f32 %0, %1;" : "=r"(u) : "f"(f));
    return u;
}

__device__ __forceinline__ void mma_tf32(float* c, unsigned a0, unsigned a1, unsigned a2,
                                         unsigned a3, unsigned b0, unsigned b1) {
    asm volatile(
        "mma.sync.aligned.m16n8k8.row.col.f32.tf32.tf32.f32 "
        "{%0,%1,%2,%3}, {%4,%5,%6,%7}, {%8,%9}, {%0,%1,%2,%3};"
        : "+f"(c[0]), "+f"(c[1]), "+f"(c[2]), "+f"(c[3])
        : "r"(a0), "r"(a1), "r"(a2), "r"(a3), "r"(b0), "r"(b1));
}

// ================= tiny init =================
__global__ void k_init_gmax() {
    if (threadIdx.x < 2 * NHEAD) g_gmax[threadIdx.x] = -1e30f;
}

// ================= CSR build (secondary stream) =================
__global__ void k_zero_deg(int n) {
    int i = blockIdx.x * blockDim.x + threadIdx.x;
    if (i < n) g_deg[i] = 0;
}

__global__ void k_count(const int* __restrict__ ei, int E, int n) {
    int e4 = (blockIdx.x * blockDim.x + threadIdx.x) * 4;
    if (e4 + 3 < E) {
        int4 d = *(const int4*)(ei + (size_t)E + e4);
        if ((unsigned)d.x < (unsigned)n) atomicAdd(&g_deg[d.x], 1);
        if ((unsigned)d.y < (unsigned)n) atomicAdd(&g_deg[d.y], 1);
        if ((unsigned)d.z < (unsigned)n) atomicAdd(&g_deg[d.z], 1);
        if ((unsigned)d.w < (unsigned)n) atomicAdd(&g_deg[d.w], 1);
    } else {
        for (int e = e4; e < E; e++) {
            int d = ei[(size_t)E + e];
            if ((unsigned)d < (unsigned)n) atomicAdd(&g_deg[d], 1);
        }
    }
}

__global__ void k_scan_a(int n) {
    __shared__ int wsum[8];
    int base = blockIdx.x * SCAN_BLK + threadIdx.x * 4;
    int s = 0;
    if (base + 3 < n) {
        int4 v = *(const int4*)(g_deg + base);
        s = v.x + v.y + v.z + v.w;
    } else {
        for (int i = 0; i < 4; i++) if (base + i < n) s += g_deg[base + i];
    }
#pragma unroll
    for (int o = 16; o > 0; o >>= 1) s += __shfl_xor_sync(0xffffffffu, s, o);
    if ((threadIdx.x & 31) == 0) wsum[threadIdx.x >> 5] = s;
    __syncthreads();
    if (threadIdx.x == 0) {
        int t = 0;
#pragma unroll
        for (int i = 0; i < 8; i++) t += wsum[i];
        g_bsum[blockIdx.x] = t;
    }
}

__global__ void k_scan_b(int nb, int n) {
    if (threadIdx.x == 0) {
        int run = 0;
        for (int i = 0; i < nb; i++) {
            g_boff[i] = run;
            run += g_bsum[i];
        }
        g_rowptr[n] = run;
    }
}

__global__ void k_scan_c(int n) {
    __shared__ int woff[8];
    int tid = threadIdx.x;
    int base = blockIdx.x * SCAN_BLK + tid * 4;

    int d0 = 0, d1 = 0, d2 = 0, d3 = 0;
    if (base + 3 < n) {
        int4 v = *(const int4*)(g_deg + base);
        d0 = v.x; d1 = v.y; d2 = v.z; d3 = v.w;
    } else {
        if (base + 0 < n) d0 = g_deg[base + 0];
        if (base + 1 < n) d1 = g_deg[base + 1];
        if (base + 2 < n) d2 = g_deg[base + 2];
        if (base + 3 < n) d3 = g_deg[base + 3];
    }
    int ts = d0 + d1 + d2 + d3;

    int inc = ts;
#pragma unroll
    for (int o = 1; o < 32; o <<= 1) {
        int v = __shfl_up_sync(0xffffffffu, inc, o);
        if ((tid & 31) >= o) inc += v;
    }
    if ((tid & 31) == 31) woff[tid >> 5] = inc;
    __syncthreads();
    if (tid < 8) {
        int v = woff[tid];
        int e = 0;
        for (int i = 0; i < 8; i++) { int u = __shfl_sync(0xffu, v, i, 8); if (i < tid) e += u; }
        woff[tid] = e;
    }
    __syncthreads();
    int excl = inc - ts + woff[tid >> 5] + g_boff[blockIdx.x];

    int p0 = excl, p1 = p0 + d0, p2 = p1 + d1, p3 = p2 + d2;
    if (base + 3 < n) {
        int4 pv = make_int4(p0, p1, p2, p3);
        *(int4*)(g_rowptr + base) = pv;
        *(int4*)(g_cursor + base) = pv;
    } else {
        if (base + 0 < n) { g_rowptr[base + 0] = p0; g_cursor[base + 0] = p0; }
        if (base + 1 < n) { g_rowptr[base + 1] = p1; g_cursor[base + 1] = p1; }
        if (base + 2 < n) { g_rowptr[base + 2] = p2; g_cursor[base + 2] = p2; }
        if (base + 3 < n) { g_rowptr[base + 3] = p3; g_cursor[base + 3] = p3; }
    }
}

__global__ void k_scatter(const int* __restrict__ ei, int E, int n) {
    int e4 = (blockIdx.x * blockDim.x + threadIdx.x) * 4;
    if (e4 + 3 < E) {
        int4 s = *(const int4*)(ei + e4);
        int4 d = *(const int4*)(ei + (size_t)E + e4);
        if ((unsigned)s.x < (unsigned)n && (unsigned)d.x < (unsigned)n)
            g_csr_src[atomicAdd(&g_cursor[d.x], 1)] = s.x;
        if ((unsigned)s.y < (unsigned)n && (unsigned)d.y < (unsigned)n)
            g_csr_src[atomicAdd(&g_cursor[d.y], 1)] = s.y;
        if ((unsigned)s.z < (unsigned)n && (unsigned)d.z < (unsigned)n)
            g_csr_src[atomicAdd(&g_cursor[d.z], 1)] = s.z;
        if ((unsigned)s.w < (unsigned)n && (unsigned)d.w < (unsigned)n)
            g_csr_src[atomicAdd(&g_cursor[d.w], 1)] = s.w;
    } else {
        for (int e = e4; e < E; e++) {
            int s = ei[e];
            int d = ei[(size_t)E + e];
            if ((unsigned)s < (unsigned)n && (unsigned)d < (unsigned)n)
                g_csr_src[atomicAdd(&g_cursor[d], 1)] = s;
        }
    }
}

// ================= tf32 tensor-core GEMM + alpha/gmax epilogue =================
// Processes rows [row_base, row_end); grid covers (row_end-row_base+63)/64 blocks.
__global__ void gemm128_tc(const float* __restrict__ A, const float* __restrict__ W,
                           float* __restrict__ Out, __half* __restrict__ Out16,
                           const float* __restrict__ a_s, const float* __restrict__ a_d,
                           float* __restrict__ asv, float* __restrict__ adv,
                           float* __restrict__ gmax4, int row_base, int row_end) {
    __shared__ unsigned xs[64 * 36];
    __shared__ unsigned ws[32 * 136];
    __shared__ float smax[NHEAD];
    int tid = threadIdx.x;
    int lane = tid & 31;
    int wid = tid >> 5;
    int gid = lane >> 2;
    int tig = lane & 3;
    int rw = wid >> 1;
    int cw = wid & 1;
    int row0 = row_base + blockIdx.x * 64;
    if (tid < NHEAD) smax[tid] = -1e30f;

    float acc[8][4];
#pragma unroll
    for (int nt = 0; nt < 8; nt++)
#pragma unroll
        for (int q = 0; q < 4; q++) acc[nt][q] = 0.f;

    for (int kc = 0; kc < 128; kc += 32) {
#pragma unroll
        for (int i = 0; i < 2; i++) {
            int idx = tid + i * 256;
            int r = idx >> 3;
            int kq = idx & 7;
            float4 v = make_float4(0.f, 0.f, 0.f, 0.f);
            if (row0 + r < row_end)
                v = *(const float4*)(A + (size_t)(row0 + r) * 128 + kc + kq * 4);
            uint4 u = make_uint4(f2tf32(v.x), f2tf32(v.y), f2tf32(v.z), f2tf32(v.w));
            *(uint4*)&xs[r * 36 + kq * 4] = u;
        }
#pragma unroll
        for (int i = 0; i < 4; i++) {
            int idx = tid + i * 256;
            int k = idx >> 5;
            int cq = idx & 31;
            float4 v = *(const float4*)(W + (size_t)(kc + k) * 128 + cq * 4);
            uint4 u = make_uint4(f2tf32(v.x), f2tf32(v.y), f2tf32(v.z), f2tf32(v.w));
            *(uint4*)&ws[k * 136 + cq * 4] = u;
        }
        __syncthreads();

        int ar0 = (rw * 16 + gid) * 36;
        int ar1 = (rw * 16 + gid + 8) * 36;
        int cb = cw * 64 + gid;
#pragma unroll
        for (int kk = 0; kk < 32; kk += 8) {
            unsigned a0 = xs[ar0 + kk + tig];
            unsigned a1 = xs[ar1 + kk + tig];
            unsigned a2 = xs[ar0 + kk + tig + 4];
            unsigned a3 = xs[ar1 + kk + tig + 4];
            int wr0 = (kk + tig) * 136;
            int wr1 = (kk + tig + 4) * 136;
#pragma unroll
            for (int nt = 0; nt < 8; nt++) {
                unsigned b0 = ws[wr0 + cb + nt * 8];
                unsigned b1 = ws[wr1 + cb + nt * 8];
                mma_tf32(acc[nt], a0, a1, a2, a3, b0, b1);
            }
        }
        __syncthreads();
    }

    int r_lo = row0 + rw * 16 + gid;
    int r_hi = r_lo + 8;
    int hA = 2 * cw, hB = 2 * cw + 1;

    float psA_lo = 0.f, psB_lo = 0.f, pdA_lo = 0.f, pdB_lo = 0.f;
    float psA_hi = 0.f, psB_hi = 0.f, pdA_hi = 0.f, pdB_hi = 0.f;

#pragma unroll
    for (int nt = 0; nt < 8; nt++) {
        int c = cw * 64 + nt * 8 + 2 * tig;
        float as0 = a_s[c], as1 = a_s[c + 1];
        float ad0 = a_d[c], ad1 = a_d[c + 1];
        if (r_lo < row_end) {
            *(float2*)(Out + (size_t)r_lo * 128 + c) = make_float2(acc[nt][0], acc[nt][1]);
            __half2 h = __floats2half2_rn(acc[nt][0], acc[nt][1]);
            *(__half2*)(Out16 + (size_t)r_lo * 128 + c) = h;
        }
        if (r_hi < row_end) {
            *(float2*)(Out + (size_t)r_hi * 128 + c) = make_float2(acc[nt][2], acc[nt][3]);
            __half2 h = __floats2half2_rn(acc[nt][2], acc[nt][3]);
            *(__half2*)(Out16 + (size_t)r_hi * 128 + c) = h;
        }
        float s_lo = acc[nt][0] * as0 + acc[nt][1] * as1;
        float d_lo = acc[nt][0] * ad0 + acc[nt][1] * ad1;
        float s_hi = acc[nt][2] * as0 + acc[nt][3] * as1;
        float d_hi = acc[nt][2] * ad0 + acc[nt][3] * ad1;
        if (nt < 4) { psA_lo += s_lo; pdA_lo += d_lo; psA_hi += s_hi; pdA_hi += d_hi; }
        else        { psB_lo += s_lo; pdB_lo += d_lo; psB_hi += s_hi; pdB_hi += d_hi; }
    }
#pragma unroll
    for (int o = 1; o < 4; o <<= 1) {
        psA_lo += __shfl_xor_sync(0xffffffffu, psA_lo, o);
        psB_lo += __shfl_xor_sync(0xffffffffu, psB_lo, o);
        pdA_lo += __shfl_xor_sync(0xffffffffu, pdA_lo, o);
        pdB_lo += __shfl_xor_sync(0xffffffffu, pdB_lo, o);
        psA_hi += __shfl_xor_sync(0xffffffffu, psA_hi, o);
        psB_hi += __shfl_xor_sync(0xffffffffu, psB_hi, o);
        pdA_hi += __shfl_xor_sync(0xffffffffu, pdA_hi, o);
        pdB_hi += __shfl_xor_sync(0xffffffffu, pdB_hi, o);
    }
    if (tig == 0) {
        if (r_lo < row_end) {
            asv[(size_t)r_lo * 4 + hA] = psA_lo;
            asv[(size_t)r_lo * 4 + hB] = psB_lo;
            adv[(size_t)r_lo * 4 + hA] = pdA_lo;
            adv[(size_t)r_lo * 4 + hB] = pdB_lo;
            atomicMaxF(&smax[hA], psA_lo);
            atomicMaxF(&smax[hB], psB_lo);
        }
        if (r_hi < row_end) {
            asv[(size_t)r_hi * 4 + hA] = psA_hi;
            asv[(size_t)r_hi * 4 + hB] = psB_hi;
            adv[(size_t)r_hi * 4 + hA] = pdA_hi;
            adv[(size_t)r_hi * 4 + hB] = pdB_hi;
            atomicMaxF(&smax[hA], psA_hi);
            atomicMaxF(&smax[hB], psB_hi);
        }
    }
    __syncthreads();
    if (tid < NHEAD) atomicMaxF(&gmax4[tid], smax[tid]);
}

// ================= aggregate body (software-pipelined, pointer-parameterized) =================
__device__ __forceinline__ void run_node(const float* __restrict__ b, float* __restrict__ outf,
                                         const float* __restrict__ gmax4,
                                         const float* __restrict__ sfw,
                                         const float* __restrict__ fcb,
                                         const float* __restrict__ hfp, const __half* __restrict__ h16,
                                         const float* __restrict__ asv, const float* __restrict__ adv,
                                         int node_base, int node_end) {
    int w = node_base + ((blockIdx.x * blockDim.x + threadIdx.x) >> 5);
    if (w >= node_end) return;
    int lane = threadIdx.x & 31;
    int head = lane >> 3;
    int hbase = lane & 24;
    int sub = lane & 7;

    int beg = g_rowptr[w];
    int end = g_rowptr[w + 1];

    float4 add4 = *(const float4*)(adv + (size_t)w * 4);
    float4 asd4 = *(const float4*)(asv + (size_t)w * 4);
    float4 gm   = *(const float4*)gmax4;

    float adh = head == 0 ? add4.x : head == 1 ? add4.y : head == 2 ? add4.z : add4.w;
    float ash = head == 0 ? asd4.x : head == 1 ? asd4.y : head == 2 ? asd4.z : asd4.w;
    float gmh = head == 0 ? gm.x   : head == 1 ? gm.y   : head == 2 ? gm.z   : gm.w;
    float sh  = lrelu02(gmh + adh);

    float den = 0.f;
    float4 acc = make_float4(0.f, 0.f, 0.f, 0.f);

    int sidx_n = 0;
    float a_n = 0.f;
    {
        int j = beg + sub;
        if (j < end) {
            sidx_n = g_csr_src[j];
            a_n = asv[(size_t)sidx_n * 4 + head];
        }
    }

    for (int c = beg; c < end; c += 8) {
        int sidx = sidx_n;
        float a = a_n;
        bool valid = (c + sub) < end;
        int jn = c + 8 + sub;
        if (jn < end) {
            sidx_n = g_csr_src[jn];
            a_n = asv[(size_t)sidx_n * 4 + head];
        }
        float ex1 = valid ? __expf(lrelu02(a + adh) - sh) : 0.f;
        den += ex1;

        int cnt = min(8, end - c);
        if (cnt == 8) {
            int   sk[8];
            float ek[8];
#pragma unroll
            for (int u = 0; u < 8; u++) {
                sk[u] = __shfl_sync(0xffffffffu, sidx, hbase + u);
                ek[u] = __shfl_sync(0xffffffffu, ex1,  hbase + u);
            }
            uint2 hv[8];
#pragma unroll
            for (int u = 0; u < 8; u++)
                hv[u] = ((const uint2*)(h16 + (size_t)sk[u] * 128))[lane];
#pragma unroll
            for (int u = 0; u < 8; u++) {
                float2 f0 = __half22float2(*(__half2*)&hv[u].x);
                float2 f1 = __half22float2(*(__half2*)&hv[u].y);
                acc.x += ek[u] * f0.x; acc.y += ek[u] * f0.y;
                acc.z += ek[u] * f1.x; acc.w += ek[u] * f1.y;
            }
        } else {
            for (int u = 0; u < cnt; u++) {
                int   sk = __shfl_sync(0xffffffffu, sidx, hbase + u);
                float ek = __shfl_sync(0xffffffffu, ex1,  hbase + u);
                uint2 hu = ((const uint2*)(h16 + (size_t)sk * 128))[lane];
                float2 f0 = __half22float2(*(__half2*)&hu.x);
                float2 f1 = __half22float2(*(__half2*)&hu.y);
                acc.x += ek * f0.x; acc.y += ek * f0.y;
                acc.z += ek * f1.x; acc.w += ek * f1.y;
            }
        }
    }
    den += __shfl_xor_sync(0xffffffffu, den, 1);
    den += __shfl_xor_sync(0xffffffffu, den, 2);
    den += __shfl_xor_sync(0xffffffffu, den, 4);

    float exs = __expf(lrelu02(ash + adh) - sh);
    den += exs;
    float inv = 1.f / (den + 1e-16f);

    float4 hself = ((const float4*)(hfp + (size_t)w * 128))[lane];
    float4 bv = ((const float4*)b)[lane];
    float4 o;
    o.x = (acc.x + exs * hself.x) * inv + bv.x;
    o.y = (acc.y + exs * hself.y) * inv + bv.y;
    o.z = (acc.z + exs * hself.z) * inv + bv.z;
    o.w = (acc.w + exs * hself.w) * inv + bv.w;
    o.x = o.x > 0.f ? o.x : expm1f(o.x);
    o.y = o.y > 0.f ? o.y : expm1f(o.y);
    o.z = o.z > 0.f ? o.z : expm1f(o.z);
    o.w = o.w > 0.f ? o.w : expm1f(o.w);

    if (sfw == nullptr) {
        ((float4*)(outf + (size_t)w * 128))[lane] = o;
    } else {
        float fa = fcb[lane];
#pragma unroll 8
        for (int r = 0; r < 32; r++) {
            float fx = __shfl_sync(0xffffffffu, o.x, r);
            float fy = __shfl_sync(0xffffffffu, o.y, r);
            float fz = __shfl_sync(0xffffffffu, o.z, r);
            float fw2 = __shfl_sync(0xffffffffu, o.w, r);
            int kb = r * 4;
            fa += fx * sfw[kb * 32 + lane] + fy * sfw[(kb + 1) * 32 + lane]
                + fz * sfw[(kb + 2) * 32 + lane] + fw2 * sfw[(kb + 3) * 32 + lane];
        }
        outf[(size_t)w * 32 + lane] = fa;
    }
}

template <bool FUSE>
__global__ void gat_aggregate(const float* __restrict__ b, float* __restrict__ outf,
                              const float* __restrict__ gmax4,
                              const float* __restrict__ fcw, const float* __restrict__ fcb,
                              const float* __restrict__ hfp, const __half* __restrict__ h16,
                              const float* __restrict__ asv, const float* __restrict__ adv,
                              int node_base, int node_end) {
    if constexpr (FUSE) {
        __shared__ float sfw[HID * 32];
#pragma unroll
        for (int i = 0; i < 4; i++)
            ((float4*)sfw)[threadIdx.x + i * 256] = ((const float4*)fcw)[threadIdx.x + i * 256];
        __syncthreads();
        run_node(b, outf, gmax4, sfw, fcb, hfp, h16, asv, adv, node_base, node_end);
    } else {
        run_node(b, outf, gmax4, (const float*)nullptr, fcb, hfp, h16, asv, adv, node_base, node_end);
    }
}

// ================= launch =================
extern "C" void kernel_launch(void* const* d_in, const int* in_sizes, int n_in,
                              void* d_out, int out_size) {
    const float* x    = (const float*)d_in[0];
    const int*   ei   = (const int*)d_in[1];
    const float* W1   = (const float*)d_in[2];
    const float* a_s1 = (const float*)d_in[3];
    const float* a_d1 = (const float*)d_in[4];
    const float* b1   = (const float*)d_in[5];
    const float* W2   = (const float*)d_in[6];
    const float* a_s2 = (const float*)d_in[7];
    const float* a_d2 = (const float*)d_in[8];
    const float* b2   = (const float*)d_in[9];
    const float* fc_w = (const float*)d_in[10];
    const float* fc_b = (const float*)d_in[11];
    float* out = (float*)d_out;

    int n = in_sizes[0] / HID;
    int E = in_sizes[1] / 2;

    float *p_h, *p_hB, *p_feat, *p_gmax, *p_as, *p_ad, *p_asB, *p_adB;
    __half *p_h16, *p_h16B;
    cudaGetSymbolAddress((void**)&p_h, g_h);
    cudaGetSymbolAddress((void**)&p_hB, g_hB);
    cudaGetSymbolAddress((void**)&p_h16, g_h16);
    cudaGetSymbolAddress((void**)&p_h16B, g_h16B);
    cudaGetSymbolAddress((void**)&p_feat, g_feat);
    cudaGetSymbolAddress((void**)&p_gmax, g_gmax);
    cudaGetSymbolAddress((void**)&p_as, g_as);
    cudaGetSymbolAddress((void**)&p_ad, g_ad);
    cudaGetSymbolAddress((void**)&p_asB, g_asB);
    cudaGetSymbolAddress((void**)&p_adB, g_adB);

    static cudaStream_t sB = nullptr;
    static cudaEvent_t evF = nullptr, evJ = nullptr, evG = nullptr;
    static cudaEvent_t evA[NCHUNK];
    if (sB == nullptr) {
        cudaStreamCreateWithFlags(&sB, cudaStreamNonBlocking);
        cudaEventCreateWithFlags(&evF, cudaEventDisableTiming);
        cudaEventCreateWithFlags(&evJ, cudaEventDisableTiming);
        cudaEventCreateWithFlags(&evG, cudaEventDisableTiming);
        for (int c = 0; c < NCHUNK; c++)
            cudaEventCreateWithFlags(&evA[c], cudaEventDisableTiming);
    }

    int edge4_grid = ((E + 3) / 4 + 255) / 256;
    int node_grid = (n + 255) / 256;
    int scan_nb   = (n + SCAN_BLK - 1) / SCAN_BLK;
    int csz = (((n + NCHUNK - 1) / NCHUNK) + 63) & ~63;   // chunk size, 64-aligned

    k_init_gmax<<<1, 32>>>();

    // ---- fork: CSR build chain on sB, overlapped with gemm1 ----
    cudaEventRecord(evF, 0);
    cudaStreamWaitEvent(sB, evF, 0);
    k_zero_deg<<<node_grid, 256, 0, sB>>>(n);
    k_count<<<edge4_grid, 256, 0, sB>>>(ei, E, n);
    k_scan_a<<<scan_nb, 256, 0, sB>>>(n);
    k_scan_b<<<1, 32, 0, sB>>>(scan_nb, n);
    k_scan_c<<<scan_nb, 256, 0, sB>>>(n);
    k_scatter<<<edge4_grid, 256, 0, sB>>>(ei, E, n);
    cudaEventRecord(evJ, sB);

    // ---- layer 1 GEMM (full) overlapped with CSR build ----
    gemm128_tc<<<(n + 63) / 64, 256>>>(x, W1, p_h, p_h16, a_s1, a_d1,
                                       p_as, p_ad, p_gmax, 0, n);
    cudaStreamWaitEvent(0, evJ, 0);

    // ---- agg1 in chunks on stream 0; gemm2 chunk follows each on sB ----
    for (int c = 0; c < NCHUNK; c++) {
        int nb = c * csz;
        int ne = min(nb + csz, n);
        if (nb >= ne) { cudaEventRecord(evA[c], 0); continue; }
        int wg = ((ne - nb) * 32 + 255) / 256;
        gat_aggregate<false><<<wg, 256>>>(b1, p_feat, p_gmax, nullptr, nullptr,
                                          p_h, p_h16, p_as, p_ad, nb, ne);
        cudaEventRecord(evA[c], 0);
        cudaStreamWaitEvent(sB, evA[c], 0);
        gemm128_tc<<<(ne - nb + 63) / 64, 256, 0, sB>>>(p_feat, W2, p_hB, p_h16B,
                                                        a_s2, a_d2, p_asB, p_adB,
                                                        p_gmax + 4, nb, ne);
    }
    cudaEventRecord(evG, sB);
    cudaStreamWaitEvent(0, evG, 0);

    // ---- layer 2 aggregate (FC fused), reads layer-2 buffers ----
    int warp_grid = (n * 32 + 255) / 256;
    gat_aggregate<true><<<warp_grid, 256>>>(b2, out, p_gmax + 4, fc_w, fc_b,
                                            p_hB, p_h16B, p_asB, p_adB, 0, n);
}

// round 14
// speedup vs baseline: 1.1852x; 1.1852x over previous
#include <cuda_runtime.h>
#include <cuda_fp16.h>
#include <cstdint>

#define NMAX 50000
#define EMAX 800000
#define HID 128
#define NHEAD 4
#define SCAN_BLK 1024
#define SCAN_NB ((NMAX + SCAN_BLK - 1) / SCAN_BLK)

// ---------------- scratch (device globals; allocation-free) ----------------
__device__ __half g_h16[(size_t)NMAX * HID];    // projected features (fp16, sole copy)
__device__ float  g_feat[(size_t)NMAX * HID];   // layer-1 output after ELU (fp32)
__device__ float  g_as[(size_t)NMAX * NHEAD];
__device__ float  g_ad[(size_t)NMAX * NHEAD];
__device__ float  g_gmax[2 * NHEAD];
__device__ int    g_deg[NMAX];
__device__ int    g_rowptr[NMAX + 1];
__device__ int    g_cursor[NMAX];
__device__ int    g_csr_src[EMAX];
__device__ int    g_bsum[SCAN_NB];
__device__ int    g_boff[SCAN_NB];

__device__ __forceinline__ float lrelu02(float v) { return v > 0.f ? v : 0.2f * v; }

__device__ __forceinline__ void atomicMaxF(float* a, float v) {
    if (v >= 0.f) atomicMax((int*)a, __float_as_int(v));
    else          atomicMin((unsigned int*)a, __float_as_uint(v));
}

__device__ __forceinline__ unsigned f2tf32(float f) {
    unsigned u;
    asm("cvt.rna.tf32.f32 %0, %1;" : "=r"(u) : "f"(f));
    return u;
}

__device__ __forceinline__ void mma_tf32(float* c, unsigned a0, unsigned a1, unsigned a2,
                                         unsigned a3, unsigned b0, unsigned b1) {
    asm volatile(
        "mma.sync.aligned.m16n8k8.row.col.f32.tf32.tf32.f32 "
        "{%0,%1,%2,%3}, {%4,%5,%6,%7}, {%8,%9}, {%0,%1,%2,%3};"
        : "+f"(c[0]), "+f"(c[1]), "+f"(c[2]), "+f"(c[3])
        : "r"(a0), "r"(a1), "r"(a2), "r"(a3), "r"(b0), "r"(b1));
}

// ================= tiny init =================
__global__ void k_init_gmax() {
    if (threadIdx.x < 2 * NHEAD) g_gmax[threadIdx.x] = -1e30f;
}

// ================= CSR build (secondary stream) =================
__global__ void k_zero_deg(int n) {
    int i = blockIdx.x * blockDim.x + threadIdx.x;
    if (i < n) g_deg[i] = 0;
}

__global__ void k_count(const int* __restrict__ ei, int E, int n) {
    int e4 = (blockIdx.x * blockDim.x + threadIdx.x) * 4;
    if (e4 + 3 < E) {
        int4 d = *(const int4*)(ei + (size_t)E + e4);
        if ((unsigned)d.x < (unsigned)n) atomicAdd(&g_deg[d.x], 1);
        if ((unsigned)d.y < (unsigned)n) atomicAdd(&g_deg[d.y], 1);
        if ((unsigned)d.z < (unsigned)n) atomicAdd(&g_deg[d.z], 1);
        if ((unsigned)d.w < (unsigned)n) atomicAdd(&g_deg[d.w], 1);
    } else {
        for (int e = e4; e < E; e++) {
            int d = ei[(size_t)E + e];
            if ((unsigned)d < (unsigned)n) atomicAdd(&g_deg[d], 1);
        }
    }
}

__global__ void k_scan_a(int n) {
    __shared__ int wsum[8];
    int base = blockIdx.x * SCAN_BLK + threadIdx.x * 4;
    int s = 0;
    if (base + 3 < n) {
        int4 v = *(const int4*)(g_deg + base);
        s = v.x + v.y + v.z + v.w;
    } else {
        for (int i = 0; i < 4; i++) if (base + i < n) s += g_deg[base + i];
    }
#pragma unroll
    for (int o = 16; o > 0; o >>= 1) s += __shfl_xor_sync(0xffffffffu, s, o);
    if ((threadIdx.x & 31) == 0) wsum[threadIdx.x >> 5] = s;
    __syncthreads();
    if (threadIdx.x == 0) {
        int t = 0;
#pragma unroll
        for (int i = 0; i < 8; i++) t += wsum[i];
        g_bsum[blockIdx.x] = t;
    }
}

__global__ void k_scan_b(int nb, int n) {
    if (threadIdx.x == 0) {
        int run = 0;
        for (int i = 0; i < nb; i++) {
            g_boff[i] = run;
            run += g_bsum[i];
        }
        g_rowptr[n] = run;
    }
}

__global__ void k_scan_c(int n) {
    __shared__ int woff[8];
    int tid = threadIdx.x;
    int base = blockIdx.x * SCAN_BLK + tid * 4;

    int d0 = 0, d1 = 0, d2 = 0, d3 = 0;
    if (base + 3 < n) {
        int4 v = *(const int4*)(g_deg + base);
        d0 = v.x; d1 = v.y; d2 = v.z; d3 = v.w;
    } else {
        if (base + 0 < n) d0 = g_deg[base + 0];
        if (base + 1 < n) d1 = g_deg[base + 1];
        if (base + 2 < n) d2 = g_deg[base + 2];
        if (base + 3 < n) d3 = g_deg[base + 3];
    }
    int ts = d0 + d1 + d2 + d3;

    int inc = ts;
#pragma unroll
    for (int o = 1; o < 32; o <<= 1) {
        int v = __shfl_up_sync(0xffffffffu, inc, o);
        if ((tid & 31) >= o) inc += v;
    }
    if ((tid & 31) == 31) woff[tid >> 5] = inc;
    __syncthreads();
    if (tid < 8) {
        int v = woff[tid];
        int e = 0;
        for (int i = 0; i < 8; i++) { int u = __shfl_sync(0xffu, v, i, 8); if (i < tid) e += u; }
        woff[tid] = e;
    }
    __syncthreads();
    int excl = inc - ts + woff[tid >> 5] + g_boff[blockIdx.x];

    int p0 = excl, p1 = p0 + d0, p2 = p1 + d1, p3 = p2 + d2;
    if (base + 3 < n) {
        int4 pv = make_int4(p0, p1, p2, p3);
        *(int4*)(g_rowptr + base) = pv;
        *(int4*)(g_cursor + base) = pv;
    } else {
        if (base + 0 < n) { g_rowptr[base + 0] = p0; g_cursor[base + 0] = p0; }
        if (base + 1 < n) { g_rowptr[base + 1] = p1; g_cursor[base + 1] = p1; }
        if (base + 2 < n) { g_rowptr[base + 2] = p2; g_cursor[base + 2] = p2; }
        if (base + 3 < n) { g_rowptr[base + 3] = p3; g_cursor[base + 3] = p3; }
    }
}

__global__ void k_scatter(const int* __restrict__ ei, int E, int n) {
    int e4 = (blockIdx.x * blockDim.x + threadIdx.x) * 4;
    if (e4 + 3 < E) {
        int4 s = *(const int4*)(ei + e4);
        int4 d = *(const int4*)(ei + (size_t)E + e4);
        if ((unsigned)s.x < (unsigned)n && (unsigned)d.x < (unsigned)n)
            g_csr_src[atomicAdd(&g_cursor[d.x], 1)] = s.x;
        if ((unsigned)s.y < (unsigned)n && (unsigned)d.y < (unsigned)n)
            g_csr_src[atomicAdd(&g_cursor[d.y], 1)] = s.y;
        if ((unsigned)s.z < (unsigned)n && (unsigned)d.z < (unsigned)n)
            g_csr_src[atomicAdd(&g_cursor[d.z], 1)] = s.z;
        if ((unsigned)s.w < (unsigned)n && (unsigned)d.w < (unsigned)n)
            g_csr_src[atomicAdd(&g_cursor[d.w], 1)] = s.w;
    } else {
        for (int e = e4; e < E; e++) {
            int s = ei[e];
            int d = ei[(size_t)E + e];
            if ((unsigned)s < (unsigned)n && (unsigned)d < (unsigned)n)
                g_csr_src[atomicAdd(&g_cursor[d], 1)] = s;
        }
    }
}

// ================= tf32 tensor-core GEMM + alpha/gmax epilogue =================
// Stores ONLY fp16 h (fp32 copy eliminated — self-loop reads fp16 too).
__global__ void gemm128_tc(const float* __restrict__ A, const float* __restrict__ W,
                           __half* __restrict__ Out16,
                           const float* __restrict__ a_s, const float* __restrict__ a_d,
                           float* __restrict__ gmax4, int n) {
    __shared__ unsigned xs[64 * 36];
    __shared__ unsigned ws[32 * 136];
    __shared__ float smax[NHEAD];
    int tid = threadIdx.x;
    int lane = tid & 31;
    int wid = tid >> 5;
    int gid = lane >> 2;
    int tig = lane & 3;
    int rw = wid >> 1;
    int cw = wid & 1;
    int row0 = blockIdx.x * 64;
    if (tid < NHEAD) smax[tid] = -1e30f;

    float acc[8][4];
#pragma unroll
    for (int nt = 0; nt < 8; nt++)
#pragma unroll
        for (int q = 0; q < 4; q++) acc[nt][q] = 0.f;

    for (int kc = 0; kc < 128; kc += 32) {
#pragma unroll
        for (int i = 0; i < 2; i++) {
            int idx = tid + i * 256;
            int r = idx >> 3;
            int kq = idx & 7;
            float4 v = make_float4(0.f, 0.f, 0.f, 0.f);
            if (row0 + r < n)
                v = *(const float4*)(A + (size_t)(row0 + r) * 128 + kc + kq * 4);
            uint4 u = make_uint4(f2tf32(v.x), f2tf32(v.y), f2tf32(v.z), f2tf32(v.w));
            *(uint4*)&xs[r * 36 + kq * 4] = u;
        }
#pragma unroll
        for (int i = 0; i < 4; i++) {
            int idx = tid + i * 256;
            int k = idx >> 5;
            int cq = idx & 31;
            float4 v = *(const float4*)(W + (size_t)(kc + k) * 128 + cq * 4);
            uint4 u = make_uint4(f2tf32(v.x), f2tf32(v.y), f2tf32(v.z), f2tf32(v.w));
            *(uint4*)&ws[k * 136 + cq * 4] = u;
        }
        __syncthreads();

        int ar0 = (rw * 16 + gid) * 36;
        int ar1 = (rw * 16 + gid + 8) * 36;
        int cb = cw * 64 + gid;
#pragma unroll
        for (int kk = 0; kk < 32; kk += 8) {
            unsigned a0 = xs[ar0 + kk + tig];
            unsigned a1 = xs[ar1 + kk + tig];
            unsigned a2 = xs[ar0 + kk + tig + 4];
            unsigned a3 = xs[ar1 + kk + tig + 4];
            int wr0 = (kk + tig) * 136;
            int wr1 = (kk + tig + 4) * 136;
#pragma unroll
            for (int nt = 0; nt < 8; nt++) {
                unsigned b0 = ws[wr0 + cb + nt * 8];
                unsigned b1 = ws[wr1 + cb + nt * 8];
                mma_tf32(acc[nt], a0, a1, a2, a3, b0, b1);
            }
        }
        __syncthreads();
    }

    int r_lo = row0 + rw * 16 + gid;
    int r_hi = r_lo + 8;
    int hA = 2 * cw, hB = 2 * cw + 1;

    float psA_lo = 0.f, psB_lo = 0.f, pdA_lo = 0.f, pdB_lo = 0.f;
    float psA_hi = 0.f, psB_hi = 0.f, pdA_hi = 0.f, pdB_hi = 0.f;

#pragma unroll
    for (int nt = 0; nt < 8; nt++) {
        int c = cw * 64 + nt * 8 + 2 * tig;
        float as0 = a_s[c], as1 = a_s[c + 1];
        float ad0 = a_d[c], ad1 = a_d[c + 1];
        if (r_lo < n) {
            __half2 h = __floats2half2_rn(acc[nt][0], acc[nt][1]);
            *(__half2*)(Out16 + (size_t)r_lo * 128 + c) = h;
        }
        if (r_hi < n) {
            __half2 h = __floats2half2_rn(acc[nt][2], acc[nt][3]);
            *(__half2*)(Out16 + (size_t)r_hi * 128 + c) = h;
        }
        float s_lo = acc[nt][0] * as0 + acc[nt][1] * as1;
        float d_lo = acc[nt][0] * ad0 + acc[nt][1] * ad1;
        float s_hi = acc[nt][2] * as0 + acc[nt][3] * as1;
        float d_hi = acc[nt][2] * ad0 + acc[nt][3] * ad1;
        if (nt < 4) { psA_lo += s_lo; pdA_lo += d_lo; psA_hi += s_hi; pdA_hi += d_hi; }
        else        { psB_lo += s_lo; pdB_lo += d_lo; psB_hi += s_hi; pdB_hi += d_hi; }
    }
#pragma unroll
    for (int o = 1; o < 4; o <<= 1) {
        psA_lo += __shfl_xor_sync(0xffffffffu, psA_lo, o);
        psB_lo += __shfl_xor_sync(0xffffffffu, psB_lo, o);
        pdA_lo += __shfl_xor_sync(0xffffffffu, pdA_lo, o);
        pdB_lo += __shfl_xor_sync(0xffffffffu, pdB_lo, o);
        psA_hi += __shfl_xor_sync(0xffffffffu, psA_hi, o);
        psB_hi += __shfl_xor_sync(0xffffffffu, psB_hi, o);
        pdA_hi += __shfl_xor_sync(0xffffffffu, pdA_hi, o);
        pdB_hi += __shfl_xor_sync(0xffffffffu, pdB_hi, o);
    }
    if (tig == 0) {
        if (r_lo < n) {
            g_as[(size_t)r_lo * 4 + hA] = psA_lo;
            g_as[(size_t)r_lo * 4 + hB] = psB_lo;
            g_ad[(size_t)r_lo * 4 + hA] = pdA_lo;
            g_ad[(size_t)r_lo * 4 + hB] = pdB_lo;
            atomicMaxF(&smax[hA], psA_lo);
            atomicMaxF(&smax[hB], psB_lo);
        }
        if (r_hi < n) {
            g_as[(size_t)r_hi * 4 + hA] = psA_hi;
            g_as[(size_t)r_hi * 4 + hB] = psB_hi;
            g_ad[(size_t)r_hi * 4 + hA] = pdA_hi;
            g_ad[(size_t)r_hi * 4 + hB] = pdB_hi;
            atomicMaxF(&smax[hA], psA_hi);
            atomicMaxF(&smax[hB], psB_hi);
        }
    }
    __syncthreads();
    if (tid < NHEAD) atomicMaxF(&gmax4[tid], smax[tid]);
}

// ================= aggregate body (software-pipelined) =================
__device__ __forceinline__ void run_node(const float* __restrict__ b, float* __restrict__ outf,
                                         const float* __restrict__ gmax4,
                                         const float* __restrict__ sfw,
                                         const float* __restrict__ fcb, int n) {
    int w = (blockIdx.x * blockDim.x + threadIdx.x) >> 5;
    if (w >= n) return;
    int lane = threadIdx.x & 31;
    int head = lane >> 3;
    int hbase = lane & 24;
    int sub = lane & 7;

    int beg = g_rowptr[w];
    int end = g_rowptr[w + 1];

    float4 add4 = *(const float4*)(g_ad + (size_t)w * 4);
    float4 asd4 = *(const float4*)(g_as + (size_t)w * 4);
    float4 gm   = *(const float4*)gmax4;

    float adh = head == 0 ? add4.x : head == 1 ? add4.y : head == 2 ? add4.z : add4.w;
    float ash = head == 0 ? asd4.x : head == 1 ? asd4.y : head == 2 ? asd4.z : asd4.w;
    float gmh = head == 0 ? gm.x   : head == 1 ? gm.y   : head == 2 ? gm.z   : gm.w;
    float sh  = lrelu02(gmh + adh);

    float den = 0.f;
    float4 acc = make_float4(0.f, 0.f, 0.f, 0.f);

    int sidx_n = 0;
    float a_n = 0.f;
    {
        int j = beg + sub;
        if (j < end) {
            sidx_n = g_csr_src[j];
            a_n = g_as[(size_t)sidx_n * 4 + head];
        }
    }

    for (int c = beg; c < end; c += 8) {
        int sidx = sidx_n;
        float a = a_n;
        bool valid = (c + sub) < end;
        int jn = c + 8 + sub;
        if (jn < end) {
            sidx_n = g_csr_src[jn];
            a_n = g_as[(size_t)sidx_n * 4 + head];
        }
        float ex1 = valid ? __expf(lrelu02(a + adh) - sh) : 0.f;
        den += ex1;

        int cnt = min(8, end - c);
        if (cnt == 8) {
            int   sk[8];
            float ek[8];
#pragma unroll
            for (int u = 0; u < 8; u++) {
                sk[u] = __shfl_sync(0xffffffffu, sidx, hbase + u);
                ek[u] = __shfl_sync(0xffffffffu, ex1,  hbase + u);
            }
            uint2 hv[8];
#pragma unroll
            for (int u = 0; u < 8; u++)
                hv[u] = ((const uint2*)(g_h16 + (size_t)sk[u] * 128))[lane];
#pragma unroll
            for (int u = 0; u < 8; u++) {
                float2 f0 = __half22float2(*(__half2*)&hv[u].x);
                float2 f1 = __half22float2(*(__half2*)&hv[u].y);
                acc.x += ek[u] * f0.x; acc.y += ek[u] * f0.y;
                acc.z += ek[u] * f1.x; acc.w += ek[u] * f1.y;
            }
        } else {
            for (int u = 0; u < cnt; u++) {
                int   sk = __shfl_sync(0xffffffffu, sidx, hbase + u);
                float ek = __shfl_sync(0xffffffffu, ex1,  hbase + u);
                uint2 hu = ((const uint2*)(g_h16 + (size_t)sk * 128))[lane];
                float2 f0 = __half22float2(*(__half2*)&hu.x);
                float2 f1 = __half22float2(*(__half2*)&hu.y);
                acc.x += ek * f0.x; acc.y += ek * f0.y;
                acc.z += ek * f1.x; acc.w += ek * f1.y;
            }
        }
    }
    den += __shfl_xor_sync(0xffffffffu, den, 1);
    den += __shfl_xor_sync(0xffffffffu, den, 2);
    den += __shfl_xor_sync(0xffffffffu, den, 4);

    float exs = __expf(lrelu02(ash + adh) - sh);
    den += exs;
    float inv = 1.f / (den + 1e-16f);

    // self-loop message from fp16 (fp32 copy eliminated)
    uint2 hs = ((const uint2*)(g_h16 + (size_t)w * 128))[lane];
    float2 s0 = __half22float2(*(__half2*)&hs.x);
    float2 s1 = __half22float2(*(__half2*)&hs.y);
    float4 bv = ((const float4*)b)[lane];
    float4 o;
    o.x = (acc.x + exs * s0.x) * inv + bv.x;
    o.y = (acc.y + exs * s0.y) * inv + bv.y;
    o.z = (acc.z + exs * s1.x) * inv + bv.z;
    o.w = (acc.w + exs * s1.y) * inv + bv.w;
    o.x = o.x > 0.f ? o.x : expm1f(o.x);
    o.y = o.y > 0.f ? o.y : expm1f(o.y);
    o.z = o.z > 0.f ? o.z : expm1f(o.z);
    o.w = o.w > 0.f ? o.w : expm1f(o.w);

    if (sfw == nullptr) {
        ((float4*)(outf + (size_t)w * 128))[lane] = o;
    } else {
        float fa = fcb[lane];
#pragma unroll 8
        for (int r = 0; r < 32; r++) {
            float fx = __shfl_sync(0xffffffffu, o.x, r);
            float fy = __shfl_sync(0xffffffffu, o.y, r);
            float fz = __shfl_sync(0xffffffffu, o.z, r);
            float fw2 = __shfl_sync(0xffffffffu, o.w, r);
            int kb = r * 4;
            fa += fx * sfw[kb * 32 + lane] + fy * sfw[(kb + 1) * 32 + lane]
                + fz * sfw[(kb + 2) * 32 + lane] + fw2 * sfw[(kb + 3) * 32 + lane];
        }
        outf[(size_t)w * 32 + lane] = fa;
    }
}

template <bool FUSE>
__global__ void gat_aggregate(const float* __restrict__ b, float* __restrict__ outf,
                              const float* __restrict__ gmax4,
                              const float* __restrict__ fcw, const float* __restrict__ fcb,
                              int n) {
    if constexpr (FUSE) {
        __shared__ float sfw[HID * 32];
#pragma unroll
        for (int i = 0; i < 4; i++)
            ((float4*)sfw)[threadIdx.x + i * 256] = ((const float4*)fcw)[threadIdx.x + i * 256];
        __syncthreads();
        run_node(b, outf, gmax4, sfw, fcb, n);
    } else {
        run_node(b, outf, gmax4, (const float*)nullptr, fcb, n);
    }
}

// ================= launch =================
extern "C" void kernel_launch(void* const* d_in, const int* in_sizes, int n_in,
                              void* d_out, int out_size) {
    const float* x    = (const float*)d_in[0];
    const int*   ei   = (const int*)d_in[1];
    const float* W1   = (const float*)d_in[2];
    const float* a_s1 = (const float*)d_in[3];
    const float* a_d1 = (const float*)d_in[4];
    const float* b1   = (const float*)d_in[5];
    const float* W2   = (const float*)d_in[6];
    const float* a_s2 = (const float*)d_in[7];
    const float* a_d2 = (const float*)d_in[8];
    const float* b2   = (const float*)d_in[9];
    const float* fc_w = (const float*)d_in[10];
    const float* fc_b = (const float*)d_in[11];
    float* out = (float*)d_out;

    int n = in_sizes[0] / HID;
    int E = in_sizes[1] / 2;

    float *p_feat, *p_gmax;
    __half* p_h16;
    cudaGetSymbolAddress((void**)&p_h16, g_h16);
    cudaGetSymbolAddress((void**)&p_feat, g_feat);
    cudaGetSymbolAddress((void**)&p_gmax, g_gmax);

    static cudaStream_t sB = nullptr;
    static cudaEvent_t evF = nullptr, evJ = nullptr;
    if (sB == nullptr) {
        cudaStreamCreateWithFlags(&sB, cudaStreamNonBlocking);
        cudaEventCreateWithFlags(&evF, cudaEventDisableTiming);
        cudaEventCreateWithFlags(&evJ, cudaEventDisableTiming);
    }

    int gemm_grid = (n + 63) / 64;
    int warp_grid = (n * 32 + 255) / 256;
    int edge4_grid = ((E + 3) / 4 + 255) / 256;
    int node_grid = (n + 255) / 256;
    int scan_nb   = (n + SCAN_BLK - 1) / SCAN_BLK;

    k_init_gmax<<<1, 32>>>();

    // ---- fork: CSR build chain on sB, overlapped with gemm1 ----
    cudaEventRecord(evF, 0);
    cudaStreamWaitEvent(sB, evF, 0);
    k_zero_deg<<<node_grid, 256, 0, sB>>>(n);
    k_count<<<edge4_grid, 256, 0, sB>>>(ei, E, n);
    k_scan_a<<<scan_nb, 256, 0, sB>>>(n);
    k_scan_b<<<1, 32, 0, sB>>>(scan_nb, n);
    k_scan_c<<<scan_nb, 256, 0, sB>>>(n);
    k_scatter<<<edge4_grid, 256, 0, sB>>>(ei, E, n);
    cudaEventRecord(evJ, sB);

    // ---- layer 1 ----
    gemm128_tc<<<gemm_grid, 256>>>(x, W1, p_h16, a_s1, a_d1, p_gmax, n);
    cudaStreamWaitEvent(0, evJ, 0);
    gat_aggregate<false><<<warp_grid, 256>>>(b1, p_feat, p_gmax, nullptr, nullptr, n);

    // ---- layer 2 (FC fused into aggregation) ----
    gemm128_tc<<<gemm_grid, 256>>>(p_feat, W2, p_h16, a_s2, a_d2, p_gmax + 4, n);
    gat_aggregate<true><<<warp_grid, 256>>>(b2, out, p_gmax + 4, fc_w, fc_b, n);
}

// round 15
// speedup vs baseline: 1.1876x; 1.0021x over previous
#include <cuda_runtime.h>
#include <cuda_fp16.h>
#include <cstdint>

#define NMAX 50000
#define EMAX 800000
#define HID 128
#define NHEAD 4
#define SCAN_BLK 1024
#define SCAN_NB ((NMAX + SCAN_BLK - 1) / SCAN_BLK)

// ---------------- scratch (device globals; allocation-free) ----------------
__device__ __half g_h16[(size_t)NMAX * HID];     // projected features (fp16, sole copy)
__device__ __half g_feat16[(size_t)NMAX * HID];  // layer-1 output after ELU (fp16)
__device__ float  g_as[(size_t)NMAX * NHEAD];
__device__ float  g_ad[(size_t)NMAX * NHEAD];
__device__ float  g_gmax[2 * NHEAD];
__device__ int    g_deg[NMAX];
__device__ int    g_rowptr[NMAX + 1];
__device__ int    g_cursor[NMAX];
__device__ unsigned short g_csr_src[EMAX];       // src indices fit in uint16 (n<65536)
__device__ int    g_bsum[SCAN_NB];
__device__ int    g_boff[SCAN_NB];

__device__ __forceinline__ float lrelu02(float v) { return v > 0.f ? v : 0.2f * v; }

__device__ __forceinline__ void atomicMaxF(float* a, float v) {
    if (v >= 0.f) atomicMax((int*)a, __float_as_int(v));
    else          atomicMin((unsigned int*)a, __float_as_uint(v));
}

__device__ __forceinline__ unsigned f2tf32(float f) {
    unsigned u;
    asm("cvt.rna.tf32.f32 %0, %1;" : "=r"(u) : "f"(f));
    return u;
}

__device__ __forceinline__ void mma_tf32(float* c, unsigned a0, unsigned a1, unsigned a2,
                                         unsigned a3, unsigned b0, unsigned b1) {
    asm volatile(
        "mma.sync.aligned.m16n8k8.row.col.f32.tf32.tf32.f32 "
        "{%0,%1,%2,%3}, {%4,%5,%6,%7}, {%8,%9}, {%0,%1,%2,%3};"
        : "+f"(c[0]), "+f"(c[1]), "+f"(c[2]), "+f"(c[3])
        : "r"(a0), "r"(a1), "r"(a2), "r"(a3), "r"(b0), "r"(b1));
}

// ================= tiny init =================
__global__ void k_init_gmax() {
    if (threadIdx.x < 2 * NHEAD) g_gmax[threadIdx.x] = -1e30f;
}

// ================= CSR build (secondary stream) =================
__global__ void k_zero_deg(int n) {
    int i = blockIdx.x * blockDim.x + threadIdx.x;
    if (i < n) g_deg[i] = 0;
}

// 8 edges per thread: two int4 loads, 8 atomics in flight
__global__ void k_count(const int* __restrict__ ei, int E, int n) {
    int e8 = (blockIdx.x * blockDim.x + threadIdx.x) * 8;
    if (e8 + 7 < E) {
        int4 d0 = *(const int4*)(ei + (size_t)E + e8);
        int4 d1 = *(const int4*)(ei + (size_t)E + e8 + 4);
        if ((unsigned)d0.x < (unsigned)n) atomicAdd(&g_deg[d0.x], 1);
        if ((unsigned)d0.y < (unsigned)n) atomicAdd(&g_deg[d0.y], 1);
        if ((unsigned)d0.z < (unsigned)n) atomicAdd(&g_deg[d0.z], 1);
        if ((unsigned)d0.w < (unsigned)n) atomicAdd(&g_deg[d0.w], 1);
        if ((unsigned)d1.x < (unsigned)n) atomicAdd(&g_deg[d1.x], 1);
        if ((unsigned)d1.y < (unsigned)n) atomicAdd(&g_deg[d1.y], 1);
        if ((unsigned)d1.z < (unsigned)n) atomicAdd(&g_deg[d1.z], 1);
        if ((unsigned)d1.w < (unsigned)n) atomicAdd(&g_deg[d1.w], 1);
    } else {
        for (int e = e8; e < E; e++) {
            int d = ei[(size_t)E + e];
            if ((unsigned)d < (unsigned)n) atomicAdd(&g_deg[d], 1);
        }
    }
}

__global__ void k_scan_a(int n) {
    __shared__ int wsum[8];
    int base = blockIdx.x * SCAN_BLK + threadIdx.x * 4;
    int s = 0;
    if (base + 3 < n) {
        int4 v = *(const int4*)(g_deg + base);
        s = v.x + v.y + v.z + v.w;
    } else {
        for (int i = 0; i < 4; i++) if (base + i < n) s += g_deg[base + i];
    }
#pragma unroll
    for (int o = 16; o > 0; o >>= 1) s += __shfl_xor_sync(0xffffffffu, s, o);
    if ((threadIdx.x & 31) == 0) wsum[threadIdx.x >> 5] = s;
    __syncthreads();
    if (threadIdx.x == 0) {
        int t = 0;
#pragma unroll
        for (int i = 0; i < 8; i++) t += wsum[i];
        g_bsum[blockIdx.x] = t;
    }
}

__global__ void k_scan_b(int nb, int n) {
    if (threadIdx.x == 0) {
        int run = 0;
        for (int i = 0; i < nb; i++) {
            g_boff[i] = run;
            run += g_bsum[i];
        }
        g_rowptr[n] = run;
    }
}

__global__ void k_scan_c(int n) {
    __shared__ int woff[8];
    int tid = threadIdx.x;
    int base = blockIdx.x * SCAN_BLK + tid * 4;

    int d0 = 0, d1 = 0, d2 = 0, d3 = 0;
    if (base + 3 < n) {
        int4 v = *(const int4*)(g_deg + base);
        d0 = v.x; d1 = v.y; d2 = v.z; d3 = v.w;
    } else {
        if (base + 0 < n) d0 = g_deg[base + 0];
        if (base + 1 < n) d1 = g_deg[base + 1];
        if (base + 2 < n) d2 = g_deg[base + 2];
        if (base + 3 < n) d3 = g_deg[base + 3];
    }
    int ts = d0 + d1 + d2 + d3;

    int inc = ts;
#pragma unroll
    for (int o = 1; o < 32; o <<= 1) {
        int v = __shfl_up_sync(0xffffffffu, inc, o);
        if ((tid & 31) >= o) inc += v;
    }
    if ((tid & 31) == 31) woff[tid >> 5] = inc;
    __syncthreads();
    if (tid < 8) {
        int v = woff[tid];
        int e = 0;
        for (int i = 0; i < 8; i++) { int u = __shfl_sync(0xffu, v, i, 8); if (i < tid) e += u; }
        woff[tid] = e;
    }
    __syncthreads();
    int excl = inc - ts + woff[tid >> 5] + g_boff[blockIdx.x];

    int p0 = excl, p1 = p0 + d0, p2 = p1 + d1, p3 = p2 + d2;
    if (base + 3 < n) {
        int4 pv = make_int4(p0, p1, p2, p3);
        *(int4*)(g_rowptr + base) = pv;
        *(int4*)(g_cursor + base) = pv;
    } else {
        if (base + 0 < n) { g_rowptr[base + 0] = p0; g_cursor[base + 0] = p0; }
        if (base + 1 < n) { g_rowptr[base + 1] = p1; g_cursor[base + 1] = p1; }
        if (base + 2 < n) { g_rowptr[base + 2] = p2; g_cursor[base + 2] = p2; }
        if (base + 3 < n) { g_rowptr[base + 3] = p3; g_cursor[base + 3] = p3; }
    }
}

__global__ void k_scatter(const int* __restrict__ ei, int E, int n) {
    int e4 = (blockIdx.x * blockDim.x + threadIdx.x) * 4;
    if (e4 + 3 < E) {
        int4 s = *(const int4*)(ei + e4);
        int4 d = *(const int4*)(ei + (size_t)E + e4);
        if ((unsigned)s.x < (unsigned)n && (unsigned)d.x < (unsigned)n)
            g_csr_src[atomicAdd(&g_cursor[d.x], 1)] = (unsigned short)s.x;
        if ((unsigned)s.y < (unsigned)n && (unsigned)d.y < (unsigned)n)
            g_csr_src[atomicAdd(&g_cursor[d.y], 1)] = (unsigned short)s.y;
        if ((unsigned)s.z < (unsigned)n && (unsigned)d.z < (unsigned)n)
            g_csr_src[atomicAdd(&g_cursor[d.z], 1)] = (unsigned short)s.z;
        if ((unsigned)s.w < (unsigned)n && (unsigned)d.w < (unsigned)n)
            g_csr_src[atomicAdd(&g_cursor[d.w], 1)] = (unsigned short)s.w;
    } else {
        for (int e = e4; e < E; e++) {
            int s = ei[e];
            int d = ei[(size_t)E + e];
            if ((unsigned)s < (unsigned)n && (unsigned)d < (unsigned)n)
                g_csr_src[atomicAdd(&g_cursor[d], 1)] = (unsigned short)s;
        }
    }
}

// ================= tf32 tensor-core GEMM + alpha/gmax epilogue =================
// HALF_IN: A is fp16 (layer 2 reads g_feat16); otherwise fp32.
template <bool HALF_IN>
__global__ void gemm128_tc(const void* __restrict__ Ap, const float* __restrict__ W,
                           __half* __restrict__ Out16,
                           const float* __restrict__ a_s, const float* __restrict__ a_d,
                           float* __restrict__ gmax4, int n) {
    __shared__ unsigned xs[64 * 36];
    __shared__ unsigned ws[32 * 136];
    __shared__ float smax[NHEAD];
    int tid = threadIdx.x;
    int lane = tid & 31;
    int wid = tid >> 5;
    int gid = lane >> 2;
    int tig = lane & 3;
    int rw = wid >> 1;
    int cw = wid & 1;
    int row0 = blockIdx.x * 64;
    if (tid < NHEAD) smax[tid] = -1e30f;

    float acc[8][4];
#pragma unroll
    for (int nt = 0; nt < 8; nt++)
#pragma unroll
        for (int q = 0; q < 4; q++) acc[nt][q] = 0.f;

    for (int kc = 0; kc < 128; kc += 32) {
#pragma unroll
        for (int i = 0; i < 2; i++) {
            int idx = tid + i * 256;
            int r = idx >> 3;
            int kq = idx & 7;
            uint4 u;
            if (HALF_IN) {
                uint2 hv = make_uint2(0u, 0u);
                if (row0 + r < n)
                    hv = *(const uint2*)((const __half*)Ap + (size_t)(row0 + r) * 128 + kc + kq * 4);
                float2 f0 = __half22float2(*(__half2*)&hv.x);
                float2 f1 = __half22float2(*(__half2*)&hv.y);
                u = make_uint4(f2tf32(f0.x), f2tf32(f0.y), f2tf32(f1.x), f2tf32(f1.y));
            } else {
                float4 v = make_float4(0.f, 0.f, 0.f, 0.f);
                if (row0 + r < n)
                    v = *(const float4*)((const float*)Ap + (size_t)(row0 + r) * 128 + kc + kq * 4);
                u = make_uint4(f2tf32(v.x), f2tf32(v.y), f2tf32(v.z), f2tf32(v.w));
            }
            *(uint4*)&xs[r * 36 + kq * 4] = u;
        }
#pragma unroll
        for (int i = 0; i < 4; i++) {
            int idx = tid + i * 256;
            int k = idx >> 5;
            int cq = idx & 31;
            float4 v = *(const float4*)(W + (size_t)(kc + k) * 128 + cq * 4);
            uint4 u = make_uint4(f2tf32(v.x), f2tf32(v.y), f2tf32(v.z), f2tf32(v.w));
            *(uint4*)&ws[k * 136 + cq * 4] = u;
        }
        __syncthreads();

        int ar0 = (rw * 16 + gid) * 36;
        int ar1 = (rw * 16 + gid + 8) * 36;
        int cb = cw * 64 + gid;
#pragma unroll
        for (int kk = 0; kk < 32; kk += 8) {
            unsigned a0 = xs[ar0 + kk + tig];
            unsigned a1 = xs[ar1 + kk + tig];
            unsigned a2 = xs[ar0 + kk + tig + 4];
            unsigned a3 = xs[ar1 + kk + tig + 4];
            int wr0 = (kk + tig) * 136;
            int wr1 = (kk + tig + 4) * 136;
#pragma unroll
            for (int nt = 0; nt < 8; nt++) {
                unsigned b0 = ws[wr0 + cb + nt * 8];
                unsigned b1 = ws[wr1 + cb + nt * 8];
                mma_tf32(acc[nt], a0, a1, a2, a3, b0, b1);
            }
        }
        __syncthreads();
    }

    int r_lo = row0 + rw * 16 + gid;
    int r_hi = r_lo + 8;
    int hA = 2 * cw, hB = 2 * cw + 1;

    float psA_lo = 0.f, psB_lo = 0.f, pdA_lo = 0.f, pdB_lo = 0.f;
    float psA_hi = 0.f, psB_hi = 0.f, pdA_hi = 0.f, pdB_hi = 0.f;

#pragma unroll
    for (int nt = 0; nt < 8; nt++) {
        int c = cw * 64 + nt * 8 + 2 * tig;
        float as0 = a_s[c], as1 = a_s[c + 1];
        float ad0 = a_d[c], ad1 = a_d[c + 1];
        if (r_lo < n) {
            __half2 h = __floats2half2_rn(acc[nt][0], acc[nt][1]);
            *(__half2*)(Out16 + (size_t)r_lo * 128 + c) = h;
        }
        if (r_hi < n) {
            __half2 h = __floats2half2_rn(acc[nt][2], acc[nt][3]);
            *(__half2*)(Out16 + (size_t)r_hi * 128 + c) = h;
        }
        float s_lo = acc[nt][0] * as0 + acc[nt][1] * as1;
        float d_lo = acc[nt][0] * ad0 + acc[nt][1] * ad1;
        float s_hi = acc[nt][2] * as0 + acc[nt][3] * as1;
        float d_hi = acc[nt][2] * ad0 + acc[nt][3] * ad1;
        if (nt < 4) { psA_lo += s_lo; pdA_lo += d_lo; psA_hi += s_hi; pdA_hi += d_hi; }
        else        { psB_lo += s_lo; pdB_lo += d_lo; psB_hi += s_hi; pdB_hi += d_hi; }
    }
#pragma unroll
    for (int o = 1; o < 4; o <<= 1) {
        psA_lo += __shfl_xor_sync(0xffffffffu, psA_lo, o);
        psB_lo += __shfl_xor_sync(0xffffffffu, psB_lo, o);
        pdA_lo += __shfl_xor_sync(0xffffffffu, pdA_lo, o);
        pdB_lo += __shfl_xor_sync(0xffffffffu, pdB_lo, o);
        psA_hi += __shfl_xor_sync(0xffffffffu, psA_hi, o);
        psB_hi += __shfl_xor_sync(0xffffffffu, psB_hi, o);
        pdA_hi += __shfl_xor_sync(0xffffffffu, pdA_hi, o);
        pdB_hi += __shfl_xor_sync(0xffffffffu, pdB_hi, o);
    }
    if (tig == 0) {
        if (r_lo < n) {
            g_as[(size_t)r_lo * 4 + hA] = psA_lo;
            g_as[(size_t)r_lo * 4 + hB] = psB_lo;
            g_ad[(size_t)r_lo * 4 + hA] = pdA_lo;
            g_ad[(size_t)r_lo * 4 + hB] = pdB_lo;
            atomicMaxF(&smax[hA], psA_lo);
            atomicMaxF(&smax[hB], psB_lo);
        }
        if (r_hi < n) {
            g_as[(size_t)r_hi * 4 + hA] = psA_hi;
            g_as[(size_t)r_hi * 4 + hB] = psB_hi;
            g_ad[(size_t)r_hi * 4 + hA] = pdA_hi;
            g_ad[(size_t)r_hi * 4 + hB] = pdB_hi;
            atomicMaxF(&smax[hA], psA_hi);
            atomicMaxF(&smax[hB], psB_hi);
        }
    }
    __syncthreads();
    if (tid < NHEAD) atomicMaxF(&gmax4[tid], smax[tid]);
}

// ================= aggregate body (software-pipelined) =================
// FUSE=false: write fp16 features to (half*)outp. FUSE=true: FC head to (float*)outp.
template <bool FUSE>
__device__ __forceinline__ void run_node(const float* __restrict__ b, void* __restrict__ outp,
                                         const float* __restrict__ gmax4,
                                         const float* __restrict__ sfw,
                                         const float* __restrict__ fcb, int n) {
    int w = (blockIdx.x * blockDim.x + threadIdx.x) >> 5;
    if (w >= n) return;
    int lane = threadIdx.x & 31;
    int head = lane >> 3;
    int hbase = lane & 24;
    int sub = lane & 7;

    int beg = g_rowptr[w];
    int end = g_rowptr[w + 1];

    float4 add4 = *(const float4*)(g_ad + (size_t)w * 4);
    float4 asd4 = *(const float4*)(g_as + (size_t)w * 4);
    float4 gm   = *(const float4*)gmax4;

    float adh = head == 0 ? add4.x : head == 1 ? add4.y : head == 2 ? add4.z : add4.w;
    float ash = head == 0 ? asd4.x : head == 1 ? asd4.y : head == 2 ? asd4.z : asd4.w;
    float gmh = head == 0 ? gm.x   : head == 1 ? gm.y   : head == 2 ? gm.z   : gm.w;
    float sh  = lrelu02(gmh + adh);

    float den = 0.f;
    float4 acc = make_float4(0.f, 0.f, 0.f, 0.f);

    int sidx_n = 0;
    float a_n = 0.f;
    {
        int j = beg + sub;
        if (j < end) {
            sidx_n = g_csr_src[j];
            a_n = g_as[(size_t)sidx_n * 4 + head];
        }
    }

    for (int c = beg; c < end; c += 8) {
        int sidx = sidx_n;
        float a = a_n;
        bool valid = (c + sub) < end;
        int jn = c + 8 + sub;
        if (jn < end) {
            sidx_n = g_csr_src[jn];
            a_n = g_as[(size_t)sidx_n * 4 + head];
        }
        float ex1 = valid ? __expf(lrelu02(a + adh) - sh) : 0.f;
        den += ex1;

        int cnt = min(8, end - c);
        if (cnt == 8) {
            int   sk[8];
            float ek[8];
#pragma unroll
            for (int u = 0; u < 8; u++) {
                sk[u] = __shfl_sync(0xffffffffu, sidx, hbase + u);
                ek[u] = __shfl_sync(0xffffffffu, ex1,  hbase + u);
            }
            uint2 hv[8];
#pragma unroll
            for (int u = 0; u < 8; u++)
                hv[u] = ((const uint2*)(g_h16 + (size_t)sk[u] * 128))[lane];
#pragma unroll
            for (int u = 0; u < 8; u++) {
                float2 f0 = __half22float2(*(__half2*)&hv[u].x);
                float2 f1 = __half22float2(*(__half2*)&hv[u].y);
                acc.x += ek[u] * f0.x; acc.y += ek[u] * f0.y;
                acc.z += ek[u] * f1.x; acc.w += ek[u] * f1.y;
            }
        } else {
            for (int u = 0; u < cnt; u++) {
                int   sk = __shfl_sync(0xffffffffu, sidx, hbase + u);
                float ek = __shfl_sync(0xffffffffu, ex1,  hbase + u);
                uint2 hu = ((const uint2*)(g_h16 + (size_t)sk * 128))[lane];
                float2 f0 = __half22float2(*(__half2*)&hu.x);
                float2 f1 = __half22float2(*(__half2*)&hu.y);
                acc.x += ek * f0.x; acc.y += ek * f0.y;
                acc.z += ek * f1.x; acc.w += ek * f1.y;
            }
        }
    }
    den += __shfl_xor_sync(0xffffffffu, den, 1);
    den += __shfl_xor_sync(0xffffffffu, den, 2);
    den += __shfl_xor_sync(0xffffffffu, den, 4);

    float exs = __expf(lrelu02(ash + adh) - sh);
    den += exs;
    float inv = 1.f / (den + 1e-16f);

    // self-loop message from fp16
    uint2 hs = ((const uint2*)(g_h16 + (size_t)w * 128))[lane];
    float2 s0 = __half22float2(*(__half2*)&hs.x);
    float2 s1 = __half22float2(*(__half2*)&hs.y);
    float4 bv = ((const float4*)b)[lane];
    float4 o;
    o.x = (acc.x + exs * s0.x) * inv + bv.x;
    o.y = (acc.y + exs * s0.y) * inv + bv.y;
    o.z = (acc.z + exs * s1.x) * inv + bv.z;
    o.w = (acc.w + exs * s1.y) * inv + bv.w;
    o.x = o.x > 0.f ? o.x : expm1f(o.x);
    o.y = o.y > 0.f ? o.y : expm1f(o.y);
    o.z = o.z > 0.f ? o.z : expm1f(o.z);
    o.w = o.w > 0.f ? o.w : expm1f(o.w);

    if (!FUSE) {
        __half2 h0 = __floats2half2_rn(o.x, o.y);
        __half2 h1 = __floats2half2_rn(o.z, o.w);
        uint2 u;
        u.x = *(unsigned int*)&h0;
        u.y = *(unsigned int*)&h1;
        ((uint2*)((__half*)outp + (size_t)w * 128))[lane] = u;
    } else {
        float fa = fcb[lane];
#pragma unroll 8
        for (int r = 0; r < 32; r++) {
            float fx = __shfl_sync(0xffffffffu, o.x, r);
            float fy = __shfl_sync(0xffffffffu, o.y, r);
            float fz = __shfl_sync(0xffffffffu, o.z, r);
            float fw2 = __shfl_sync(0xffffffffu, o.w, r);
            int kb = r * 4;
            fa += fx * sfw[kb * 32 + lane] + fy * sfw[(kb + 1) * 32 + lane]
                + fz * sfw[(kb + 2) * 32 + lane] + fw2 * sfw[(kb + 3) * 32 + lane];
        }
        ((float*)outp)[(size_t)w * 32 + lane] = fa;
    }
}

template <bool FUSE>
__global__ void gat_aggregate(const float* __restrict__ b, void* __restrict__ outp,
                              const float* __restrict__ gmax4,
                              const float* __restrict__ fcw, const float* __restrict__ fcb,
                              int n) {
    if constexpr (FUSE) {
        __shared__ float sfw[HID * 32];
#pragma unroll
        for (int i = 0; i < 4; i++)
            ((float4*)sfw)[threadIdx.x + i * 256] = ((const float4*)fcw)[threadIdx.x + i * 256];
        __syncthreads();
        run_node<true>(b, outp, gmax4, sfw, fcb, n);
    } else {
        run_node<false>(b, outp, gmax4, (const float*)nullptr, fcb, n);
    }
}

// ================= launch =================
extern "C" void kernel_launch(void* const* d_in, const int* in_sizes, int n_in,
                              void* d_out, int out_size) {
    const float* x    = (const float*)d_in[0];
    const int*   ei   = (const int*)d_in[1];
    const float* W1   = (const float*)d_in[2];
    const float* a_s1 = (const float*)d_in[3];
    const float* a_d1 = (const float*)d_in[4];
    const float* b1   = (const float*)d_in[5];
    const float* W2   = (const float*)d_in[6];
    const float* a_s2 = (const float*)d_in[7];
    const float* a_d2 = (const float*)d_in[8];
    const float* b2   = (const float*)d_in[9];
    const float* fc_w = (const float*)d_in[10];
    const float* fc_b = (const float*)d_in[11];
    float* out = (float*)d_out;

    int n = in_sizes[0] / HID;
    int E = in_sizes[1] / 2;

    float *p_gmax;
    __half *p_h16, *p_feat16;
    cudaGetSymbolAddress((void**)&p_h16, g_h16);
    cudaGetSymbolAddress((void**)&p_feat16, g_feat16);
    cudaGetSymbolAddress((void**)&p_gmax, g_gmax);

    static cudaStream_t sB = nullptr;
    static cudaEvent_t evF = nullptr, evJ = nullptr;
    if (sB == nullptr) {
        cudaStreamCreateWithFlags(&sB, cudaStreamNonBlocking);
        cudaEventCreateWithFlags(&evF, cudaEventDisableTiming);
        cudaEventCreateWithFlags(&evJ, cudaEventDisableTiming);
    }

    int gemm_grid = (n + 63) / 64;
    int warp_grid = (n * 32 + 255) / 256;
    int edge4_grid = ((E + 3) / 4 + 255) / 256;
    int edge8_grid = ((E + 7) / 8 + 255) / 256;
    int node_grid = (n + 255) / 256;
    int scan_nb   = (n + SCAN_BLK - 1) / SCAN_BLK;

    k_init_gmax<<<1, 32>>>();

    // ---- fork: CSR build chain on sB, overlapped with gemm1 ----
    cudaEventRecord(evF, 0);
    cudaStreamWaitEvent(sB, evF, 0);
    k_zero_deg<<<node_grid, 256, 0, sB>>>(n);
    k_count<<<edge8_grid, 256, 0, sB>>>(ei, E, n);
    k_scan_a<<<scan_nb, 256, 0, sB>>>(n);
    k_scan_b<<<1, 32, 0, sB>>>(scan_nb, n);
    k_scan_c<<<scan_nb, 256, 0, sB>>>(n);
    k_scatter<<<edge4_grid, 256, 0, sB>>>(ei, E, n);
    cudaEventRecord(evJ, sB);

    // ---- layer 1 ----
    gemm128_tc<false><<<gemm_grid, 256>>>(x, W1, p_h16, a_s1, a_d1, p_gmax, n);
    cudaStreamWaitEvent(0, evJ, 0);
    gat_aggregate<false><<<warp_grid, 256>>>(b1, p_feat16, p_gmax, nullptr, nullptr, n);

    // ---- layer 2 (FC fused into aggregation) ----
    gemm128_tc<true><<<gemm_grid, 256>>>(p_feat16, W2, p_h16, a_s2, a_d2, p_gmax + 4, n);
    gat_aggregate<true><<<warp_grid, 256>>>(b2, out, p_gmax + 4, fc_w, fc_b, n);
}